// round 15
// baseline (speedup 1.0000x reference)
#include <cuda_runtime.h>
#include <cuda_fp16.h>
#include <cstdint>

#define T_SEQ 4096
#define C_DIM 1024
#define NH    16
#define DHEAD 64
#define BANDW 128

// ---------------------------------------------------------------------------
// Scratch (__device__ globals; allocation-free rule)
// ---------------------------------------------------------------------------
__device__ __half g_x[T_SEQ * C_DIM];
__device__ __half g_q[T_SEQ * C_DIM];
__device__ __half g_k[T_SEQ * C_DIM];
__device__ __half g_v[T_SEQ * C_DIM];
__device__ __half g_a[T_SEQ * C_DIM];
__device__ __half g_w[4][C_DIM * C_DIM];

// ---------------------------------------------------------------------------
// PTX helpers (base features only — compute_103 PTX target)
// ---------------------------------------------------------------------------
__device__ __forceinline__ uint32_t smem_u32(const void* p) {
    uint32_t a;
    asm("{ .reg .u64 t; cvta.to.shared.u64 t, %1; cvt.u32.u64 %0, t; }" : "=r"(a) : "l"(p));
    return a;
}
__device__ __forceinline__ void cp16(uint32_t dst, const void* src) {
    asm volatile("cp.async.cg.shared.global [%0], [%1], 16;" :: "r"(dst), "l"(src));
}
__device__ __forceinline__ void cp_commit() {
    asm volatile("cp.async.commit_group;" ::: "memory");
}
__device__ __forceinline__ void stz16(uint32_t a) {
    asm volatile("st.shared.v4.u32 [%0], {%1,%1,%1,%1};" :: "r"(a), "r"(0) : "memory");
}
__device__ __forceinline__ void ldm_x4(uint32_t* r, uint32_t a) {
    asm volatile("ldmatrix.sync.aligned.m8n8.x4.shared.b16 {%0,%1,%2,%3}, [%4];"
                 : "=r"(r[0]), "=r"(r[1]), "=r"(r[2]), "=r"(r[3]) : "r"(a));
}
__device__ __forceinline__ void ldm_x4t(uint32_t* r, uint32_t a) {
    asm volatile("ldmatrix.sync.aligned.m8n8.x4.trans.shared.b16 {%0,%1,%2,%3}, [%4];"
                 : "=r"(r[0]), "=r"(r[1]), "=r"(r[2]), "=r"(r[3]) : "r"(a));
}
__device__ __forceinline__ void mma16816h(float* d, const uint32_t* a, const uint32_t* b) {
    asm volatile("mma.sync.aligned.m16n8k16.row.col.f32.f16.f16.f32 "
                 "{%0,%1,%2,%3}, {%4,%5,%6,%7}, {%8,%9}, {%0,%1,%2,%3};"
                 : "+f"(d[0]), "+f"(d[1]), "+f"(d[2]), "+f"(d[3])
                 : "r"(a[0]), "r"(a[1]), "r"(a[2]), "r"(a[3]), "r"(b[0]), "r"(b[1]));
}

// ---------------------------------------------------------------------------
// fused fp32 -> fp16 conversion: y=0 -> x, y=1..4 -> Wq/Wk/Wv/Wo
// ---------------------------------------------------------------------------
__global__ __launch_bounds__(256) void conv_all_kernel(const float* __restrict__ x,
                                                       const float* __restrict__ w0,
                                                       const float* __restrict__ w1,
                                                       const float* __restrict__ w2,
                                                       const float* __restrict__ w3,
                                                       __half* __restrict__ xo,
                                                       __half* __restrict__ wo) {
    const int y = blockIdx.y;
    const int i = blockIdx.x * 256 + threadIdx.x;
    const float* in;
    __half* out;
    int n4;
    if (y == 0) {
        in = x; out = xo; n4 = T_SEQ * C_DIM / 4;
    } else {
        in = (y == 1) ? w0 : (y == 2) ? w1 : (y == 3) ? w2 : w3;
        out = wo + (size_t)(y - 1) * (C_DIM * C_DIM);
        n4 = C_DIM * C_DIM / 4;
    }
    if (i >= n4) return;
    float4 v = ((const float4*)in)[i];
    __half2* hp = (__half2*)(out + 4 * (size_t)i);
    hp[0] = __floats2half2_rn(v.x, v.y);
    hp[1] = __floats2half2_rn(v.z, v.w);
}

// ---------------------------------------------------------------------------
// Shared GEMM mainloop (fp16 single-pass): 128x128 CTA tile, BK=64,
// 256 threads = 2x4 warps (warp tile 64x32), 3-stage cp.async ring,
// register-double-buffered fragments, 144B padded rows, 2 CTAs/SM.
// (round-13 config — local optimum for the mma.sync path; do not touch)
// ---------------------------------------------------------------------------
#define BM 128
#define BN 128
#define BK 64
#define GK C_DIM
#define NCHUNK (GK / BK)          // 16
#define ROWB 144                  // 64 fp16 = 128B data + 16B pad
#define TILEB (128 * ROWB)        // 18432 B
#define STAGEB (2 * TILEB)        // 36864 B
#define NSTAGE 3
#define GEMM_SMEM (NSTAGE * STAGEB)   // 110592 B

__device__ __forceinline__ void ldm_frags(uint32_t (&Av)[4][4], uint32_t (&Bv)[4][2],
                                          uint32_t ds, uint32_t aoff, uint32_t boff,
                                          uint32_t ka) {
    const uint32_t sA = ds + 0 * TILEB + aoff + ka;
    const uint32_t sB = ds + 1 * TILEB + boff + ka;
#pragma unroll
    for (int mt = 0; mt < 4; mt++)
        ldm_x4(Av[mt], sA + mt * (16 * ROWB));
#pragma unroll
    for (int p = 0; p < 2; p++) {
        uint32_t rb[4];
        ldm_x4(rb, sB + p * (16 * ROWB));
        Bv[2 * p][0] = rb[0]; Bv[2 * p][1] = rb[1];
        Bv[2 * p + 1][0] = rb[2]; Bv[2 * p + 1][1] = rb[3];
    }
}

__device__ __forceinline__ void mma_batch(float (&acc)[4][4][4],
                                          const uint32_t (&Av)[4][4],
                                          const uint32_t (&Bv)[4][2]) {
#pragma unroll
    for (int mt = 0; mt < 4; mt++)
#pragma unroll
        for (int nt = 0; nt < 4; nt++)
            mma16816h(acc[mt][nt], Av[mt], Bv[nt]);
}

__device__ __forceinline__ void gemm_mainloop(uint32_t sbase, int tid,
                                              const __half* __restrict__ tA,
                                              const __half* __restrict__ tB,
                                              float (&acc)[4][4][4]) {
    const int lane = tid & 31;
    const int warp = tid >> 5;
    const int warp_m = warp >> 2;
    const int warp_n = warp & 3;
    const __half* tb[2] = {tA, tB};

    auto load_stage = [&](int s, int c) {
        const int k0 = c * BK;
        const uint32_t ds = sbase + s * STAGEB;
#pragma unroll
        for (int t = 0; t < 2; t++) {
#pragma unroll
            for (int it = 0; it < 4; it++) {
                int idx = tid + it * 256;            // 0..1023
                int row = idx >> 3;
                int col = idx & 7;
                cp16(ds + t * TILEB + row * ROWB + col * 16,
                     tb[t] + (size_t)row * GK + k0 + col * 8);
            }
        }
        cp_commit();
    };

    const int sel = lane >> 3;
    const int l7  = lane & 7;
    const uint32_t aoff = (uint32_t)((warp_m * 64 + (sel & 1) * 8 + l7) * ROWB + (sel >> 1) * 16);
    const uint32_t boff = (uint32_t)((warp_n * 32 + (sel >> 1) * 8 + l7) * ROWB + (sel & 1) * 16);

    load_stage(0, 0);
    load_stage(1, 1);
    load_stage(2, 2);

    uint32_t A0[4][4], B0[4][2], A1[4][4], B1[4][2];

    asm volatile("cp.async.wait_group 2;" ::: "memory");
    __syncthreads();
    ldm_frags(A0, B0, sbase + 0 * STAGEB, aoff, boff, 0);

    for (int c = 0; c < NCHUNK; c++) {
        const uint32_t ds = sbase + (c % 3) * STAGEB;

        ldm_frags(A1, B1, ds, aoff, boff, 32);    // (c, ks1)
        mma_batch(acc, A0, B0);                   // (c, ks0)
        ldm_frags(A0, B0, ds, aoff, boff, 64);    // (c, ks2)
        mma_batch(acc, A1, B1);                   // (c, ks1)
        ldm_frags(A1, B1, ds, aoff, boff, 96);    // (c, ks3)
        mma_batch(acc, A0, B0);                   // (c, ks2)

        if (c + 1 < NCHUNK) {
            if (c < NCHUNK - 2) asm volatile("cp.async.wait_group 1;" ::: "memory");
            else                asm volatile("cp.async.wait_group 0;" ::: "memory");
            __syncthreads();
            if (c + 3 < NCHUNK) load_stage((c + 3) % 3, c + 3);
            ldm_frags(A0, B0, sbase + ((c + 1) % 3) * STAGEB, aoff, boff, 0);
        }

        mma_batch(acc, A1, B1);                   // (c, ks3)
    }
}

// ---- Fused QKV projection: all outputs single fp16 ----
__global__ __launch_bounds__(256, 2) void mma_gemm_qkv(const __half* __restrict__ x,
                                                       const __half* __restrict__ w,
                                                       __half* __restrict__ qq,
                                                       __half* __restrict__ kk,
                                                       __half* __restrict__ vv) {
    extern __shared__ __align__(128) char smem[];
    const uint32_t sbase = smem_u32(smem);
    const int tid = threadIdx.x;
    const int which = blockIdx.x >> 3;
    const int n0 = (blockIdx.x & 7) * BN;
    const int m0 = blockIdx.y * BM;
    const size_t WSZ = (size_t)C_DIM * C_DIM;

    float acc[4][4][4];
#pragma unroll
    for (int i = 0; i < 4; i++)
#pragma unroll
        for (int j = 0; j < 4; j++)
#pragma unroll
            for (int e = 0; e < 4; e++) acc[i][j][e] = 0.0f;

    gemm_mainloop(sbase, tid, x + (size_t)m0 * GK,
                  w + which * WSZ + (size_t)n0 * GK, acc);

    __half* o = (which == 0) ? qq : (which == 1) ? kk : vv;
    const int lane = tid & 31;
    const int warp = tid >> 5;
    const int warp_m = warp >> 2;
    const int warp_n = warp & 3;
    const int er = lane >> 2;
    const int ec = (lane & 3) * 2;
#pragma unroll
    for (int mt = 0; mt < 4; mt++) {
        const int row = m0 + warp_m * 64 + mt * 16 + er;
#pragma unroll
        for (int nt = 0; nt < 4; nt++) {
            const int col = n0 + warp_n * 32 + nt * 8 + ec;
#pragma unroll
            for (int hh = 0; hh < 2; hh++) {
                size_t off = (size_t)(row + 8 * hh) * C_DIM + col;
                *(__half2*)&o[off] =
                    __floats2half2_rn(acc[mt][nt][2 * hh], acc[mt][nt][2 * hh + 1]);
            }
        }
    }
}

// ---- Output projection: fp32 epilogue ----
__global__ __launch_bounds__(256, 2) void mma_gemm_f32(const __half* __restrict__ A,
                                                       const __half* __restrict__ B,
                                                       float* __restrict__ C) {
    extern __shared__ __align__(128) char smem[];
    const uint32_t sbase = smem_u32(smem);
    const int tid = threadIdx.x;
    const int n0 = blockIdx.x * BN;
    const int m0 = blockIdx.y * BM;

    float acc[4][4][4];
#pragma unroll
    for (int i = 0; i < 4; i++)
#pragma unroll
        for (int j = 0; j < 4; j++)
#pragma unroll
            for (int e = 0; e < 4; e++) acc[i][j][e] = 0.0f;

    gemm_mainloop(sbase, tid, A + (size_t)m0 * GK, B + (size_t)n0 * GK, acc);

    const int lane = tid & 31;
    const int warp = tid >> 5;
    const int warp_m = warp >> 2;
    const int warp_n = warp & 3;
    const int er = lane >> 2;
    const int ec = (lane & 3) * 2;
#pragma unroll
    for (int mt = 0; mt < 4; mt++) {
        const int row = m0 + warp_m * 64 + mt * 16 + er;
#pragma unroll
        for (int nt = 0; nt < 4; nt++) {
            const int col = n0 + warp_n * 32 + nt * 8 + ec;
            *(float2*)&C[(size_t)row * C_DIM + col] = make_float2(acc[mt][nt][0], acc[mt][nt][1]);
            *(float2*)&C[(size_t)(row + 8) * C_DIM + col] = make_float2(acc[mt][nt][2], acc[mt][nt][3]);
        }
    }
}

// ---------------------------------------------------------------------------
// Banded causal attention — flash-style, register-resident S/P (round-13),
// now targeting 3 CTAs/SM (64.5KB smem x3 = 193.5KB; reg cap 170).
// ---------------------------------------------------------------------------
#define QT 64
#define KT 192
#define AROW 144
#define OFF_Q 0
#define OFF_K 9216
#define OFF_V 36864
#define ATTN_SMEM 64512

__global__ __launch_bounds__(128, 3) void attn_mma(const __half* __restrict__ qq,
                                                   const __half* __restrict__ kk,
                                                   const __half* __restrict__ vv,
                                                   __half* __restrict__ yy) {
    extern __shared__ __align__(128) char smem[];
    const uint32_t sbase = smem_u32(smem);
    const int h   = blockIdx.y;
    const int t0  = blockIdx.x * QT;
    const int tid = threadIdx.x;
    const int hoff = h * DHEAD;

    for (int idx = tid; idx < QT * 8; idx += 128) {
        int row = idx >> 3, c = idx & 7;
        size_t src = (size_t)(t0 + row) * C_DIM + hoff + c * 8;
        cp16(sbase + OFF_Q + row * AROW + c * 16, qq + src);
    }
    for (int idx = tid; idx < KT * 8; idx += 128) {
        int row = idx >> 3, c = idx & 7;
        int jg = t0 - BANDW + row;
        uint32_t d = row * AROW + c * 16;
        if (jg >= 0) {
            size_t src = (size_t)jg * C_DIM + hoff + c * 8;
            cp16(sbase + OFF_K + d, kk + src);
            cp16(sbase + OFF_V + d, vv + src);
        } else {
            stz16(sbase + OFF_K + d);
            stz16(sbase + OFF_V + d);
        }
    }
    cp_commit();
    asm volatile("cp.async.wait_group 0;" ::: "memory");
    __syncthreads();     // the ONLY block-wide barrier

    const int lane = tid & 31;
    const int w    = tid >> 5;          // warp 0..3 -> rows 16w..16w+15
    const int sel  = lane >> 3;
    const int l7   = lane & 7;
    const int r    = lane >> 2;
    const int c2   = (lane & 3) * 2;

    float sacc[24][4];
#pragma unroll
    for (int m = 0; m < 24; m++)
#pragma unroll
        for (int e = 0; e < 4; e++) sacc[m][e] = 0.0f;

    const uint32_t sQ = sbase + OFF_Q +
        (uint32_t)((w * 16 + (sel & 1) * 8 + l7) * AROW + (sel >> 1) * 16);
    const uint32_t sK = sbase + OFF_K +
        (uint32_t)(((sel >> 1) * 8 + l7) * AROW + (sel & 1) * 16);

#pragma unroll
    for (int ks = 0; ks < 4; ks++) {
        uint32_t Qv[4];
        ldm_x4(Qv, sQ + ks * 32);
#pragma unroll
        for (int p = 0; p < 12; p++) {
            uint32_t rb[4];
            ldm_x4(rb, sK + p * (16 * AROW) + ks * 32);
            uint32_t B0[2] = {rb[0], rb[1]};
            uint32_t B1[2] = {rb[2], rb[3]};
            mma16816h(sacc[2 * p], Qv, B0);
            mma16816h(sacc[2 * p + 1], Qv, B1);
        }
    }

    const int i0 = t0 + w * 16 + r;
    const int i1 = i0 + 8;
    float mx0 = -1e30f, mx1 = -1e30f;
#pragma unroll
    for (int m = 0; m < 24; m++) {
        int j0 = 8 * m + c2;
        int jg0 = t0 - BANDW + j0, jg1 = jg0 + 1;
        bool v00 = (jg0 >= 0) && (jg0 <= i0) && ((i0 - jg0) < BANDW);
        bool v01 = (jg1 >= 0) && (jg1 <= i0) && ((i0 - jg1) < BANDW);
        bool v10 = (jg0 >= 0) && (jg0 <= i1) && ((i1 - jg0) < BANDW);
        bool v11 = (jg1 >= 0) && (jg1 <= i1) && ((i1 - jg1) < BANDW);
        sacc[m][0] = v00 ? sacc[m][0] * 0.125f : -1e30f;
        sacc[m][1] = v01 ? sacc[m][1] * 0.125f : -1e30f;
        sacc[m][2] = v10 ? sacc[m][2] * 0.125f : -1e30f;
        sacc[m][3] = v11 ? sacc[m][3] * 0.125f : -1e30f;
        mx0 = fmaxf(mx0, fmaxf(sacc[m][0], sacc[m][1]));
        mx1 = fmaxf(mx1, fmaxf(sacc[m][2], sacc[m][3]));
    }
    mx0 = fmaxf(mx0, __shfl_xor_sync(0xFFFFFFFFu, mx0, 1));
    mx0 = fmaxf(mx0, __shfl_xor_sync(0xFFFFFFFFu, mx0, 2));
    mx1 = fmaxf(mx1, __shfl_xor_sync(0xFFFFFFFFu, mx1, 1));
    mx1 = fmaxf(mx1, __shfl_xor_sync(0xFFFFFFFFu, mx1, 2));

    float sum0 = 0.0f, sum1 = 0.0f;
#pragma unroll
    for (int m = 0; m < 24; m++) {
        sacc[m][0] = __expf(sacc[m][0] - mx0);
        sacc[m][1] = __expf(sacc[m][1] - mx0);
        sacc[m][2] = __expf(sacc[m][2] - mx1);
        sacc[m][3] = __expf(sacc[m][3] - mx1);
        sum0 += sacc[m][0] + sacc[m][1];
        sum1 += sacc[m][2] + sacc[m][3];
    }
    sum0 += __shfl_xor_sync(0xFFFFFFFFu, sum0, 1);
    sum0 += __shfl_xor_sync(0xFFFFFFFFu, sum0, 2);
    sum1 += __shfl_xor_sync(0xFFFFFFFFu, sum1, 1);
    sum1 += __shfl_xor_sync(0xFFFFFFFFu, sum1, 2);
    const float inv0 = 1.0f / sum0;
    const float inv1 = 1.0f / sum1;

    uint32_t Pf[12][4];
#pragma unroll
    for (int j = 0; j < 12; j++) {
        __half2 a0 = __floats2half2_rn(sacc[2 * j][0] * inv0, sacc[2 * j][1] * inv0);
        __half2 a1 = __floats2half2_rn(sacc[2 * j][2] * inv1, sacc[2 * j][3] * inv1);
        __half2 a2 = __floats2half2_rn(sacc[2 * j + 1][0] * inv0, sacc[2 * j + 1][1] * inv0);
        __half2 a3 = __floats2half2_rn(sacc[2 * j + 1][2] * inv1, sacc[2 * j + 1][3] * inv1);
        Pf[j][0] = *(uint32_t*)&a0;
        Pf[j][1] = *(uint32_t*)&a1;
        Pf[j][2] = *(uint32_t*)&a2;
        Pf[j][3] = *(uint32_t*)&a3;
    }

    float oacc[8][4];
#pragma unroll
    for (int n = 0; n < 8; n++)
#pragma unroll
        for (int e = 0; e < 4; e++) oacc[n][e] = 0.0f;

    const uint32_t sV = sbase + OFF_V +
        (uint32_t)(((sel & 1) * 8 + l7) * AROW + (sel >> 1) * 16);
#pragma unroll
    for (int kt = 0; kt < 12; kt++) {
#pragma unroll
        for (int nb = 0; nb < 4; nb++) {
            uint32_t rb[4];
            ldm_x4t(rb, sV + kt * (16 * AROW) + nb * 32);
            uint32_t B0[2] = {rb[0], rb[1]};
            uint32_t B1[2] = {rb[2], rb[3]};
            mma16816h(oacc[2 * nb], Pf[kt], B0);
            mma16816h(oacc[2 * nb + 1], Pf[kt], B1);
        }
    }

#pragma unroll
    for (int nt = 0; nt < 8; nt++) {
        const int col = hoff + 8 * nt + c2;
        *(__half2*)&yy[(size_t)i0 * C_DIM + col] = __floats2half2_rn(oacc[nt][0], oacc[nt][1]);
        *(__half2*)&yy[(size_t)i1 * C_DIM + col] = __floats2half2_rn(oacc[nt][2], oacc[nt][3]);
    }
}

// ---------------------------------------------------------------------------
extern "C" void kernel_launch(void* const* d_in, const int* in_sizes, int n_in,
                              void* d_out, int out_size) {
    const float* x  = (const float*)d_in[0];
    const float* Wq = (const float*)d_in[1];
    const float* Wk = (const float*)d_in[2];
    const float* Wv = (const float*)d_in[3];
    const float* Wo = (const float*)d_in[4];
    float* out = (float*)d_out;

    __half *xh, *qh, *kh, *vh, *ah, *w;
    cudaGetSymbolAddress((void**)&xh, g_x);
    cudaGetSymbolAddress((void**)&qh, g_q);
    cudaGetSymbolAddress((void**)&kh, g_k);
    cudaGetSymbolAddress((void**)&vh, g_v);
    cudaGetSymbolAddress((void**)&ah, g_a);
    cudaGetSymbolAddress((void**)&w, g_w);

    cudaFuncSetAttribute(mma_gemm_qkv, cudaFuncAttributeMaxDynamicSharedMemorySize, GEMM_SMEM);
    cudaFuncSetAttribute(mma_gemm_f32, cudaFuncAttributeMaxDynamicSharedMemorySize, GEMM_SMEM);
    cudaFuncSetAttribute(attn_mma, cudaFuncAttributeMaxDynamicSharedMemorySize, ATTN_SMEM);

    const size_t WSZ = (size_t)C_DIM * C_DIM;

    conv_all_kernel<<<dim3(T_SEQ * C_DIM / 4 / 256, 5), 256>>>(x, Wq, Wk, Wv, Wo, xh, w);

    mma_gemm_qkv<<<dim3(24, 32), 256, GEMM_SMEM>>>(xh, w, qh, kh, vh);

    attn_mma<<<dim3(T_SEQ / QT, NH), 128, ATTN_SMEM>>>(qh, kh, vh, ah);

    mma_gemm_f32<<<dim3(8, 32), 256, GEMM_SMEM>>>(ah, w + 3 * WSZ, out);
}

// round 16
// speedup vs baseline: 1.4922x; 1.4922x over previous
#include <cuda_runtime.h>
#include <cuda_fp16.h>
#include <cstdint>

#define T_SEQ 4096
#define C_DIM 1024
#define NH    16
#define DHEAD 64
#define BANDW 128

// ---------------------------------------------------------------------------
// Scratch (__device__ globals; allocation-free rule)
// ---------------------------------------------------------------------------
__device__ __half g_x[T_SEQ * C_DIM];
__device__ __half g_q[T_SEQ * C_DIM];
__device__ __half g_k[T_SEQ * C_DIM];
__device__ __half g_v[T_SEQ * C_DIM];
__device__ __half g_a[T_SEQ * C_DIM];
__device__ __half g_w[4][C_DIM * C_DIM];

// ---------------------------------------------------------------------------
// PTX helpers (base features only — compute_103 PTX target)
// ---------------------------------------------------------------------------
__device__ __forceinline__ uint32_t smem_u32(const void* p) {
    uint32_t a;
    asm("{ .reg .u64 t; cvta.to.shared.u64 t, %1; cvt.u32.u64 %0, t; }" : "=r"(a) : "l"(p));
    return a;
}
__device__ __forceinline__ void cp16(uint32_t dst, const void* src) {
    asm volatile("cp.async.cg.shared.global [%0], [%1], 16;" :: "r"(dst), "l"(src));
}
__device__ __forceinline__ void cp_commit() {
    asm volatile("cp.async.commit_group;" ::: "memory");
}
__device__ __forceinline__ void stz16(uint32_t a) {
    asm volatile("st.shared.v4.u32 [%0], {%1,%1,%1,%1};" :: "r"(a), "r"(0) : "memory");
}
__device__ __forceinline__ void ldm_x4(uint32_t* r, uint32_t a) {
    asm volatile("ldmatrix.sync.aligned.m8n8.x4.shared.b16 {%0,%1,%2,%3}, [%4];"
                 : "=r"(r[0]), "=r"(r[1]), "=r"(r[2]), "=r"(r[3]) : "r"(a));
}
__device__ __forceinline__ void ldm_x4t(uint32_t* r, uint32_t a) {
    asm volatile("ldmatrix.sync.aligned.m8n8.x4.trans.shared.b16 {%0,%1,%2,%3}, [%4];"
                 : "=r"(r[0]), "=r"(r[1]), "=r"(r[2]), "=r"(r[3]) : "r"(a));
}
__device__ __forceinline__ void mma16816h(float* d, const uint32_t* a, const uint32_t* b) {
    asm volatile("mma.sync.aligned.m16n8k16.row.col.f32.f16.f16.f32 "
                 "{%0,%1,%2,%3}, {%4,%5,%6,%7}, {%8,%9}, {%0,%1,%2,%3};"
                 : "+f"(d[0]), "+f"(d[1]), "+f"(d[2]), "+f"(d[3])
                 : "r"(a[0]), "r"(a[1]), "r"(a[2]), "r"(a[3]), "r"(b[0]), "r"(b[1]));
}

// ---------------------------------------------------------------------------
// fused fp32 -> fp16 conversion: y=0 -> x, y=1..4 -> Wq/Wk/Wv/Wo
// ---------------------------------------------------------------------------
__global__ __launch_bounds__(256) void conv_all_kernel(const float* __restrict__ x,
                                                       const float* __restrict__ w0,
                                                       const float* __restrict__ w1,
                                                       const float* __restrict__ w2,
                                                       const float* __restrict__ w3,
                                                       __half* __restrict__ xo,
                                                       __half* __restrict__ wo) {
    const int y = blockIdx.y;
    const int i = blockIdx.x * 256 + threadIdx.x;
    const float* in;
    __half* out;
    int n4;
    if (y == 0) {
        in = x; out = xo; n4 = T_SEQ * C_DIM / 4;
    } else {
        in = (y == 1) ? w0 : (y == 2) ? w1 : (y == 3) ? w2 : w3;
        out = wo + (size_t)(y - 1) * (C_DIM * C_DIM);
        n4 = C_DIM * C_DIM / 4;
    }
    if (i >= n4) return;
    float4 v = ((const float4*)in)[i];
    __half2* hp = (__half2*)(out + 4 * (size_t)i);
    hp[0] = __floats2half2_rn(v.x, v.y);
    hp[1] = __floats2half2_rn(v.z, v.w);
}

// ---------------------------------------------------------------------------
// Shared GEMM mainloop (fp16 single-pass): 128x128 CTA tile, BK=64,
// 256 threads = 2x4 warps (warp tile 64x32), 3-stage cp.async ring,
// register-double-buffered fragments, 144B padded rows, 2 CTAs/SM.
// (round-13 config — local optimum for the mma.sync path; do not touch)
// ---------------------------------------------------------------------------
#define BM 128
#define BN 128
#define BK 64
#define GK C_DIM
#define NCHUNK (GK / BK)          // 16
#define ROWB 144                  // 64 fp16 = 128B data + 16B pad
#define TILEB (128 * ROWB)        // 18432 B
#define STAGEB (2 * TILEB)        // 36864 B
#define NSTAGE 3
#define GEMM_SMEM (NSTAGE * STAGEB)   // 110592 B

__device__ __forceinline__ void ldm_frags(uint32_t (&Av)[4][4], uint32_t (&Bv)[4][2],
                                          uint32_t ds, uint32_t aoff, uint32_t boff,
                                          uint32_t ka) {
    const uint32_t sA = ds + 0 * TILEB + aoff + ka;
    const uint32_t sB = ds + 1 * TILEB + boff + ka;
#pragma unroll
    for (int mt = 0; mt < 4; mt++)
        ldm_x4(Av[mt], sA + mt * (16 * ROWB));
#pragma unroll
    for (int p = 0; p < 2; p++) {
        uint32_t rb[4];
        ldm_x4(rb, sB + p * (16 * ROWB));
        Bv[2 * p][0] = rb[0]; Bv[2 * p][1] = rb[1];
        Bv[2 * p + 1][0] = rb[2]; Bv[2 * p + 1][1] = rb[3];
    }
}

__device__ __forceinline__ void mma_batch(float (&acc)[4][4][4],
                                          const uint32_t (&Av)[4][4],
                                          const uint32_t (&Bv)[4][2]) {
#pragma unroll
    for (int mt = 0; mt < 4; mt++)
#pragma unroll
        for (int nt = 0; nt < 4; nt++)
            mma16816h(acc[mt][nt], Av[mt], Bv[nt]);
}

__device__ __forceinline__ void gemm_mainloop(uint32_t sbase, int tid,
                                              const __half* __restrict__ tA,
                                              const __half* __restrict__ tB,
                                              float (&acc)[4][4][4]) {
    const int lane = tid & 31;
    const int warp = tid >> 5;
    const int warp_m = warp >> 2;
    const int warp_n = warp & 3;
    const __half* tb[2] = {tA, tB};

    auto load_stage = [&](int s, int c) {
        const int k0 = c * BK;
        const uint32_t ds = sbase + s * STAGEB;
#pragma unroll
        for (int t = 0; t < 2; t++) {
#pragma unroll
            for (int it = 0; it < 4; it++) {
                int idx = tid + it * 256;            // 0..1023
                int row = idx >> 3;
                int col = idx & 7;
                cp16(ds + t * TILEB + row * ROWB + col * 16,
                     tb[t] + (size_t)row * GK + k0 + col * 8);
            }
        }
        cp_commit();
    };

    const int sel = lane >> 3;
    const int l7  = lane & 7;
    const uint32_t aoff = (uint32_t)((warp_m * 64 + (sel & 1) * 8 + l7) * ROWB + (sel >> 1) * 16);
    const uint32_t boff = (uint32_t)((warp_n * 32 + (sel >> 1) * 8 + l7) * ROWB + (sel & 1) * 16);

    load_stage(0, 0);
    load_stage(1, 1);
    load_stage(2, 2);

    uint32_t A0[4][4], B0[4][2], A1[4][4], B1[4][2];

    asm volatile("cp.async.wait_group 2;" ::: "memory");
    __syncthreads();
    ldm_frags(A0, B0, sbase + 0 * STAGEB, aoff, boff, 0);

    for (int c = 0; c < NCHUNK; c++) {
        const uint32_t ds = sbase + (c % 3) * STAGEB;

        ldm_frags(A1, B1, ds, aoff, boff, 32);    // (c, ks1)
        mma_batch(acc, A0, B0);                   // (c, ks0)
        ldm_frags(A0, B0, ds, aoff, boff, 64);    // (c, ks2)
        mma_batch(acc, A1, B1);                   // (c, ks1)
        ldm_frags(A1, B1, ds, aoff, boff, 96);    // (c, ks3)
        mma_batch(acc, A0, B0);                   // (c, ks2)

        if (c + 1 < NCHUNK) {
            if (c < NCHUNK - 2) asm volatile("cp.async.wait_group 1;" ::: "memory");
            else                asm volatile("cp.async.wait_group 0;" ::: "memory");
            __syncthreads();
            if (c + 3 < NCHUNK) load_stage((c + 3) % 3, c + 3);
            ldm_frags(A0, B0, sbase + ((c + 1) % 3) * STAGEB, aoff, boff, 0);
        }

        mma_batch(acc, A1, B1);                   // (c, ks3)
    }
}

// ---- Fused QKV projection: all outputs single fp16 ----
__global__ __launch_bounds__(256, 2) void mma_gemm_qkv(const __half* __restrict__ x,
                                                       const __half* __restrict__ w,
                                                       __half* __restrict__ qq,
                                                       __half* __restrict__ kk,
                                                       __half* __restrict__ vv) {
    extern __shared__ __align__(128) char smem[];
    const uint32_t sbase = smem_u32(smem);
    const int tid = threadIdx.x;
    const int which = blockIdx.x >> 3;
    const int n0 = (blockIdx.x & 7) * BN;
    const int m0 = blockIdx.y * BM;
    const size_t WSZ = (size_t)C_DIM * C_DIM;

    float acc[4][4][4];
#pragma unroll
    for (int i = 0; i < 4; i++)
#pragma unroll
        for (int j = 0; j < 4; j++)
#pragma unroll
            for (int e = 0; e < 4; e++) acc[i][j][e] = 0.0f;

    gemm_mainloop(sbase, tid, x + (size_t)m0 * GK,
                  w + which * WSZ + (size_t)n0 * GK, acc);

    __half* o = (which == 0) ? qq : (which == 1) ? kk : vv;
    const int lane = tid & 31;
    const int warp = tid >> 5;
    const int warp_m = warp >> 2;
    const int warp_n = warp & 3;
    const int er = lane >> 2;
    const int ec = (lane & 3) * 2;
#pragma unroll
    for (int mt = 0; mt < 4; mt++) {
        const int row = m0 + warp_m * 64 + mt * 16 + er;
#pragma unroll
        for (int nt = 0; nt < 4; nt++) {
            const int col = n0 + warp_n * 32 + nt * 8 + ec;
#pragma unroll
            for (int hh = 0; hh < 2; hh++) {
                size_t off = (size_t)(row + 8 * hh) * C_DIM + col;
                *(__half2*)&o[off] =
                    __floats2half2_rn(acc[mt][nt][2 * hh], acc[mt][nt][2 * hh + 1]);
            }
        }
    }
}

// ---- Output projection: fp32 epilogue ----
__global__ __launch_bounds__(256, 2) void mma_gemm_f32(const __half* __restrict__ A,
                                                       const __half* __restrict__ B,
                                                       float* __restrict__ C) {
    extern __shared__ __align__(128) char smem[];
    const uint32_t sbase = smem_u32(smem);
    const int tid = threadIdx.x;
    const int n0 = blockIdx.x * BN;
    const int m0 = blockIdx.y * BM;

    float acc[4][4][4];
#pragma unroll
    for (int i = 0; i < 4; i++)
#pragma unroll
        for (int j = 0; j < 4; j++)
#pragma unroll
            for (int e = 0; e < 4; e++) acc[i][j][e] = 0.0f;

    gemm_mainloop(sbase, tid, A + (size_t)m0 * GK, B + (size_t)n0 * GK, acc);

    const int lane = tid & 31;
    const int warp = tid >> 5;
    const int warp_m = warp >> 2;
    const int warp_n = warp & 3;
    const int er = lane >> 2;
    const int ec = (lane & 3) * 2;
#pragma unroll
    for (int mt = 0; mt < 4; mt++) {
        const int row = m0 + warp_m * 64 + mt * 16 + er;
#pragma unroll
        for (int nt = 0; nt < 4; nt++) {
            const int col = n0 + warp_n * 32 + nt * 8 + ec;
            *(float2*)&C[(size_t)row * C_DIM + col] = make_float2(acc[mt][nt][0], acc[mt][nt][1]);
            *(float2*)&C[(size_t)(row + 8) * C_DIM + col] = make_float2(acc[mt][nt][2], acc[mt][nt][3]);
        }
    }
}

// ---------------------------------------------------------------------------
// Banded causal attention — flash-style, register-resident S/P (round-13,
// occupancy 2: the verified 145.8us configuration).
// ---------------------------------------------------------------------------
#define QT 64
#define KT 192
#define AROW 144
#define OFF_Q 0
#define OFF_K 9216
#define OFF_V 36864
#define ATTN_SMEM 64512

__global__ __launch_bounds__(128, 2) void attn_mma(const __half* __restrict__ qq,
                                                   const __half* __restrict__ kk,
                                                   const __half* __restrict__ vv,
                                                   __half* __restrict__ yy) {
    extern __shared__ __align__(128) char smem[];
    const uint32_t sbase = smem_u32(smem);
    const int h   = blockIdx.y;
    const int t0  = blockIdx.x * QT;
    const int tid = threadIdx.x;
    const int hoff = h * DHEAD;

    for (int idx = tid; idx < QT * 8; idx += 128) {
        int row = idx >> 3, c = idx & 7;
        size_t src = (size_t)(t0 + row) * C_DIM + hoff + c * 8;
        cp16(sbase + OFF_Q + row * AROW + c * 16, qq + src);
    }
    for (int idx = tid; idx < KT * 8; idx += 128) {
        int row = idx >> 3, c = idx & 7;
        int jg = t0 - BANDW + row;
        uint32_t d = row * AROW + c * 16;
        if (jg >= 0) {
            size_t src = (size_t)jg * C_DIM + hoff + c * 8;
            cp16(sbase + OFF_K + d, kk + src);
            cp16(sbase + OFF_V + d, vv + src);
        } else {
            stz16(sbase + OFF_K + d);
            stz16(sbase + OFF_V + d);
        }
    }
    cp_commit();
    asm volatile("cp.async.wait_group 0;" ::: "memory");
    __syncthreads();     // the ONLY block-wide barrier

    const int lane = tid & 31;
    const int w    = tid >> 5;          // warp 0..3 -> rows 16w..16w+15
    const int sel  = lane >> 3;
    const int l7   = lane & 7;
    const int r    = lane >> 2;
    const int c2   = (lane & 3) * 2;

    float sacc[24][4];
#pragma unroll
    for (int m = 0; m < 24; m++)
#pragma unroll
        for (int e = 0; e < 4; e++) sacc[m][e] = 0.0f;

    const uint32_t sQ = sbase + OFF_Q +
        (uint32_t)((w * 16 + (sel & 1) * 8 + l7) * AROW + (sel >> 1) * 16);
    const uint32_t sK = sbase + OFF_K +
        (uint32_t)(((sel >> 1) * 8 + l7) * AROW + (sel & 1) * 16);

#pragma unroll
    for (int ks = 0; ks < 4; ks++) {
        uint32_t Qv[4];
        ldm_x4(Qv, sQ + ks * 32);
#pragma unroll
        for (int p = 0; p < 12; p++) {
            uint32_t rb[4];
            ldm_x4(rb, sK + p * (16 * AROW) + ks * 32);
            uint32_t B0[2] = {rb[0], rb[1]};
            uint32_t B1[2] = {rb[2], rb[3]};
            mma16816h(sacc[2 * p], Qv, B0);
            mma16816h(sacc[2 * p + 1], Qv, B1);
        }
    }

    const int i0 = t0 + w * 16 + r;
    const int i1 = i0 + 8;
    float mx0 = -1e30f, mx1 = -1e30f;
#pragma unroll
    for (int m = 0; m < 24; m++) {
        int j0 = 8 * m + c2;
        int jg0 = t0 - BANDW + j0, jg1 = jg0 + 1;
        bool v00 = (jg0 >= 0) && (jg0 <= i0) && ((i0 - jg0) < BANDW);
        bool v01 = (jg1 >= 0) && (jg1 <= i0) && ((i0 - jg1) < BANDW);
        bool v10 = (jg0 >= 0) && (jg0 <= i1) && ((i1 - jg0) < BANDW);
        bool v11 = (jg1 >= 0) && (jg1 <= i1) && ((i1 - jg1) < BANDW);
        sacc[m][0] = v00 ? sacc[m][0] * 0.125f : -1e30f;
        sacc[m][1] = v01 ? sacc[m][1] * 0.125f : -1e30f;
        sacc[m][2] = v10 ? sacc[m][2] * 0.125f : -1e30f;
        sacc[m][3] = v11 ? sacc[m][3] * 0.125f : -1e30f;
        mx0 = fmaxf(mx0, fmaxf(sacc[m][0], sacc[m][1]));
        mx1 = fmaxf(mx1, fmaxf(sacc[m][2], sacc[m][3]));
    }
    mx0 = fmaxf(mx0, __shfl_xor_sync(0xFFFFFFFFu, mx0, 1));
    mx0 = fmaxf(mx0, __shfl_xor_sync(0xFFFFFFFFu, mx0, 2));
    mx1 = fmaxf(mx1, __shfl_xor_sync(0xFFFFFFFFu, mx1, 1));
    mx1 = fmaxf(mx1, __shfl_xor_sync(0xFFFFFFFFu, mx1, 2));

    float sum0 = 0.0f, sum1 = 0.0f;
#pragma unroll
    for (int m = 0; m < 24; m++) {
        sacc[m][0] = __expf(sacc[m][0] - mx0);
        sacc[m][1] = __expf(sacc[m][1] - mx0);
        sacc[m][2] = __expf(sacc[m][2] - mx1);
        sacc[m][3] = __expf(sacc[m][3] - mx1);
        sum0 += sacc[m][0] + sacc[m][1];
        sum1 += sacc[m][2] + sacc[m][3];
    }
    sum0 += __shfl_xor_sync(0xFFFFFFFFu, sum0, 1);
    sum0 += __shfl_xor_sync(0xFFFFFFFFu, sum0, 2);
    sum1 += __shfl_xor_sync(0xFFFFFFFFu, sum1, 1);
    sum1 += __shfl_xor_sync(0xFFFFFFFFu, sum1, 2);
    const float inv0 = 1.0f / sum0;
    const float inv1 = 1.0f / sum1;

    uint32_t Pf[12][4];
#pragma unroll
    for (int j = 0; j < 12; j++) {
        __half2 a0 = __floats2half2_rn(sacc[2 * j][0] * inv0, sacc[2 * j][1] * inv0);
        __half2 a1 = __floats2half2_rn(sacc[2 * j][2] * inv1, sacc[2 * j][3] * inv1);
        __half2 a2 = __floats2half2_rn(sacc[2 * j + 1][0] * inv0, sacc[2 * j + 1][1] * inv0);
        __half2 a3 = __floats2half2_rn(sacc[2 * j + 1][2] * inv1, sacc[2 * j + 1][3] * inv1);
        Pf[j][0] = *(uint32_t*)&a0;
        Pf[j][1] = *(uint32_t*)&a1;
        Pf[j][2] = *(uint32_t*)&a2;
        Pf[j][3] = *(uint32_t*)&a3;
    }

    float oacc[8][4];
#pragma unroll
    for (int n = 0; n < 8; n++)
#pragma unroll
        for (int e = 0; e < 4; e++) oacc[n][e] = 0.0f;

    const uint32_t sV = sbase + OFF_V +
        (uint32_t)(((sel & 1) * 8 + l7) * AROW + (sel >> 1) * 16);
#pragma unroll
    for (int kt = 0; kt < 12; kt++) {
#pragma unroll
        for (int nb = 0; nb < 4; nb++) {
            uint32_t rb[4];
            ldm_x4t(rb, sV + kt * (16 * AROW) + nb * 32);
            uint32_t B0[2] = {rb[0], rb[1]};
            uint32_t B1[2] = {rb[2], rb[3]};
            mma16816h(oacc[2 * nb], Pf[kt], B0);
            mma16816h(oacc[2 * nb + 1], Pf[kt], B1);
        }
    }

#pragma unroll
    for (int nt = 0; nt < 8; nt++) {
        const int col = hoff + 8 * nt + c2;
        *(__half2*)&yy[(size_t)i0 * C_DIM + col] = __floats2half2_rn(oacc[nt][0], oacc[nt][1]);
        *(__half2*)&yy[(size_t)i1 * C_DIM + col] = __floats2half2_rn(oacc[nt][2], oacc[nt][3]);
    }
}

// ---------------------------------------------------------------------------
extern "C" void kernel_launch(void* const* d_in, const int* in_sizes, int n_in,
                              void* d_out, int out_size) {
    const float* x  = (const float*)d_in[0];
    const float* Wq = (const float*)d_in[1];
    const float* Wk = (const float*)d_in[2];
    const float* Wv = (const float*)d_in[3];
    const float* Wo = (const float*)d_in[4];
    float* out = (float*)d_out;

    __half *xh, *qh, *kh, *vh, *ah, *w;
    cudaGetSymbolAddress((void**)&xh, g_x);
    cudaGetSymbolAddress((void**)&qh, g_q);
    cudaGetSymbolAddress((void**)&kh, g_k);
    cudaGetSymbolAddress((void**)&vh, g_v);
    cudaGetSymbolAddress((void**)&ah, g_a);
    cudaGetSymbolAddress((void**)&w, g_w);

    cudaFuncSetAttribute(mma_gemm_qkv, cudaFuncAttributeMaxDynamicSharedMemorySize, GEMM_SMEM);
    cudaFuncSetAttribute(mma_gemm_f32, cudaFuncAttributeMaxDynamicSharedMemorySize, GEMM_SMEM);
    cudaFuncSetAttribute(attn_mma, cudaFuncAttributeMaxDynamicSharedMemorySize, ATTN_SMEM);

    const size_t WSZ = (size_t)C_DIM * C_DIM;

    conv_all_kernel<<<dim3(T_SEQ * C_DIM / 4 / 256, 5), 256>>>(x, Wq, Wk, Wv, Wo, xh, w);

    mma_gemm_qkv<<<dim3(24, 32), 256, GEMM_SMEM>>>(xh, w, qh, kh, vh);

    attn_mma<<<dim3(T_SEQ / QT, NH), 128, ATTN_SMEM>>>(qh, kh, vh, ah);

    mma_gemm_f32<<<dim3(8, 32), 256, GEMM_SMEM>>>(ah, w + 3 * WSZ, out);
}

// round 17
// speedup vs baseline: 1.5233x; 1.0208x over previous
#include <cuda_runtime.h>
#include <cuda_fp16.h>
#include <cstdint>

#define T_SEQ 4096
#define C_DIM 1024
#define NH    16
#define DHEAD 64
#define BANDW 128

// ---------------------------------------------------------------------------
// Scratch (__device__ globals; allocation-free rule)
// ---------------------------------------------------------------------------
__device__ __half g_x[T_SEQ * C_DIM];
__device__ __half g_q[T_SEQ * C_DIM];
__device__ __half g_k[T_SEQ * C_DIM];
__device__ __half g_v[T_SEQ * C_DIM];
__device__ __half g_a[T_SEQ * C_DIM];
__device__ __half g_w[4][C_DIM * C_DIM];

// ---------------------------------------------------------------------------
// PTX helpers (base features only — compute_103 PTX target)
// ---------------------------------------------------------------------------
__device__ __forceinline__ uint32_t smem_u32(const void* p) {
    uint32_t a;
    asm("{ .reg .u64 t; cvta.to.shared.u64 t, %1; cvt.u32.u64 %0, t; }" : "=r"(a) : "l"(p));
    return a;
}
__device__ __forceinline__ void cp16(uint32_t dst, const void* src) {
    asm volatile("cp.async.cg.shared.global [%0], [%1], 16;" :: "r"(dst), "l"(src));
}
__device__ __forceinline__ void cp_commit() {
    asm volatile("cp.async.commit_group;" ::: "memory");
}
__device__ __forceinline__ void stz16(uint32_t a) {
    asm volatile("st.shared.v4.u32 [%0], {%1,%1,%1,%1};" :: "r"(a), "r"(0) : "memory");
}
__device__ __forceinline__ void ldm_x4(uint32_t* r, uint32_t a) {
    asm volatile("ldmatrix.sync.aligned.m8n8.x4.shared.b16 {%0,%1,%2,%3}, [%4];"
                 : "=r"(r[0]), "=r"(r[1]), "=r"(r[2]), "=r"(r[3]) : "r"(a));
}
__device__ __forceinline__ void ldm_x4t(uint32_t* r, uint32_t a) {
    asm volatile("ldmatrix.sync.aligned.m8n8.x4.trans.shared.b16 {%0,%1,%2,%3}, [%4];"
                 : "=r"(r[0]), "=r"(r[1]), "=r"(r[2]), "=r"(r[3]) : "r"(a));
}
__device__ __forceinline__ void mma16816h(float* d, const uint32_t* a, const uint32_t* b) {
    asm volatile("mma.sync.aligned.m16n8k16.row.col.f32.f16.f16.f32 "
                 "{%0,%1,%2,%3}, {%4,%5,%6,%7}, {%8,%9}, {%0,%1,%2,%3};"
                 : "+f"(d[0]), "+f"(d[1]), "+f"(d[2]), "+f"(d[3])
                 : "r"(a[0]), "r"(a[1]), "r"(a[2]), "r"(a[3]), "r"(b[0]), "r"(b[1]));
}

// ---------------------------------------------------------------------------
// fused fp32 -> fp16 conversion: y=0 -> x, y=1..4 -> Wq/Wk/Wv/Wo
// ---------------------------------------------------------------------------
__global__ __launch_bounds__(256) void conv_all_kernel(const float* __restrict__ x,
                                                       const float* __restrict__ w0,
                                                       const float* __restrict__ w1,
                                                       const float* __restrict__ w2,
                                                       const float* __restrict__ w3,
                                                       __half* __restrict__ xo,
                                                       __half* __restrict__ wo) {
    const int y = blockIdx.y;
    const int i = blockIdx.x * 256 + threadIdx.x;
    const float* in;
    __half* out;
    int n4;
    if (y == 0) {
        in = x; out = xo; n4 = T_SEQ * C_DIM / 4;
    } else {
        in = (y == 1) ? w0 : (y == 2) ? w1 : (y == 3) ? w2 : w3;
        out = wo + (size_t)(y - 1) * (C_DIM * C_DIM);
        n4 = C_DIM * C_DIM / 4;
    }
    if (i >= n4) return;
    float4 v = ((const float4*)in)[i];
    __half2* hp = (__half2*)(out + 4 * (size_t)i);
    hp[0] = __floats2half2_rn(v.x, v.y);
    hp[1] = __floats2half2_rn(v.z, v.w);
}

// ---------------------------------------------------------------------------
// Shared GEMM mainloop (fp16 single-pass): 128x128 CTA tile, BK=64,
// 256 threads = 2x4 warps (warp tile 64x32), 3-stage cp.async ring,
// register-double-buffered fragments, 144B padded rows, 2 CTAs/SM.
// (round-13 config — local optimum for the mma.sync path; do not touch)
// ---------------------------------------------------------------------------
#define BM 128
#define BN 128
#define BK 64
#define GK C_DIM
#define NCHUNK (GK / BK)          // 16
#define ROWB 144                  // 64 fp16 = 128B data + 16B pad
#define TILEB (128 * ROWB)        // 18432 B
#define STAGEB (2 * TILEB)        // 36864 B
#define NSTAGE 3
#define GEMM_SMEM (NSTAGE * STAGEB)   // 110592 B

__device__ __forceinline__ void ldm_frags(uint32_t (&Av)[4][4], uint32_t (&Bv)[4][2],
                                          uint32_t ds, uint32_t aoff, uint32_t boff,
                                          uint32_t ka) {
    const uint32_t sA = ds + 0 * TILEB + aoff + ka;
    const uint32_t sB = ds + 1 * TILEB + boff + ka;
#pragma unroll
    for (int mt = 0; mt < 4; mt++)
        ldm_x4(Av[mt], sA + mt * (16 * ROWB));
#pragma unroll
    for (int p = 0; p < 2; p++) {
        uint32_t rb[4];
        ldm_x4(rb, sB + p * (16 * ROWB));
        Bv[2 * p][0] = rb[0]; Bv[2 * p][1] = rb[1];
        Bv[2 * p + 1][0] = rb[2]; Bv[2 * p + 1][1] = rb[3];
    }
}

__device__ __forceinline__ void mma_batch(float (&acc)[4][4][4],
                                          const uint32_t (&Av)[4][4],
                                          const uint32_t (&Bv)[4][2]) {
#pragma unroll
    for (int mt = 0; mt < 4; mt++)
#pragma unroll
        for (int nt = 0; nt < 4; nt++)
            mma16816h(acc[mt][nt], Av[mt], Bv[nt]);
}

__device__ __forceinline__ void gemm_mainloop(uint32_t sbase, int tid,
                                              const __half* __restrict__ tA,
                                              const __half* __restrict__ tB,
                                              float (&acc)[4][4][4]) {
    const int lane = tid & 31;
    const int warp = tid >> 5;
    const int warp_m = warp >> 2;
    const int warp_n = warp & 3;
    const __half* tb[2] = {tA, tB};

    auto load_stage = [&](int s, int c) {
        const int k0 = c * BK;
        const uint32_t ds = sbase + s * STAGEB;
#pragma unroll
        for (int t = 0; t < 2; t++) {
#pragma unroll
            for (int it = 0; it < 4; it++) {
                int idx = tid + it * 256;            // 0..1023
                int row = idx >> 3;
                int col = idx & 7;
                cp16(ds + t * TILEB + row * ROWB + col * 16,
                     tb[t] + (size_t)row * GK + k0 + col * 8);
            }
        }
        cp_commit();
    };

    const int sel = lane >> 3;
    const int l7  = lane & 7;
    const uint32_t aoff = (uint32_t)((warp_m * 64 + (sel & 1) * 8 + l7) * ROWB + (sel >> 1) * 16);
    const uint32_t boff = (uint32_t)((warp_n * 32 + (sel >> 1) * 8 + l7) * ROWB + (sel & 1) * 16);

    load_stage(0, 0);
    load_stage(1, 1);
    load_stage(2, 2);

    uint32_t A0[4][4], B0[4][2], A1[4][4], B1[4][2];

    asm volatile("cp.async.wait_group 2;" ::: "memory");
    __syncthreads();
    ldm_frags(A0, B0, sbase + 0 * STAGEB, aoff, boff, 0);

    for (int c = 0; c < NCHUNK; c++) {
        const uint32_t ds = sbase + (c % 3) * STAGEB;

        ldm_frags(A1, B1, ds, aoff, boff, 32);    // (c, ks1)
        mma_batch(acc, A0, B0);                   // (c, ks0)
        ldm_frags(A0, B0, ds, aoff, boff, 64);    // (c, ks2)
        mma_batch(acc, A1, B1);                   // (c, ks1)
        ldm_frags(A1, B1, ds, aoff, boff, 96);    // (c, ks3)
        mma_batch(acc, A0, B0);                   // (c, ks2)

        if (c + 1 < NCHUNK) {
            if (c < NCHUNK - 2) asm volatile("cp.async.wait_group 1;" ::: "memory");
            else                asm volatile("cp.async.wait_group 0;" ::: "memory");
            __syncthreads();
            if (c + 3 < NCHUNK) load_stage((c + 3) % 3, c + 3);
            ldm_frags(A0, B0, sbase + ((c + 1) % 3) * STAGEB, aoff, boff, 0);
        }

        mma_batch(acc, A1, B1);                   // (c, ks3)
    }
}

// ---- Fused QKV projection: all outputs single fp16 ----
__global__ __launch_bounds__(256, 2) void mma_gemm_qkv(const __half* __restrict__ x,
                                                       const __half* __restrict__ w,
                                                       __half* __restrict__ qq,
                                                       __half* __restrict__ kk,
                                                       __half* __restrict__ vv) {
    extern __shared__ __align__(128) char smem[];
    const uint32_t sbase = smem_u32(smem);
    const int tid = threadIdx.x;
    const int which = blockIdx.x >> 3;
    const int n0 = (blockIdx.x & 7) * BN;
    const int m0 = blockIdx.y * BM;
    const size_t WSZ = (size_t)C_DIM * C_DIM;

    float acc[4][4][4];
#pragma unroll
    for (int i = 0; i < 4; i++)
#pragma unroll
        for (int j = 0; j < 4; j++)
#pragma unroll
            for (int e = 0; e < 4; e++) acc[i][j][e] = 0.0f;

    gemm_mainloop(sbase, tid, x + (size_t)m0 * GK,
                  w + which * WSZ + (size_t)n0 * GK, acc);

    __half* o = (which == 0) ? qq : (which == 1) ? kk : vv;
    const int lane = tid & 31;
    const int warp = tid >> 5;
    const int warp_m = warp >> 2;
    const int warp_n = warp & 3;
    const int er = lane >> 2;
    const int ec = (lane & 3) * 2;
#pragma unroll
    for (int mt = 0; mt < 4; mt++) {
        const int row = m0 + warp_m * 64 + mt * 16 + er;
#pragma unroll
        for (int nt = 0; nt < 4; nt++) {
            const int col = n0 + warp_n * 32 + nt * 8 + ec;
#pragma unroll
            for (int hh = 0; hh < 2; hh++) {
                size_t off = (size_t)(row + 8 * hh) * C_DIM + col;
                *(__half2*)&o[off] =
                    __floats2half2_rn(acc[mt][nt][2 * hh], acc[mt][nt][2 * hh + 1]);
            }
        }
    }
}

// ---- Output projection: fp32 epilogue ----
__global__ __launch_bounds__(256, 2) void mma_gemm_f32(const __half* __restrict__ A,
                                                       const __half* __restrict__ B,
                                                       float* __restrict__ C) {
    extern __shared__ __align__(128) char smem[];
    const uint32_t sbase = smem_u32(smem);
    const int tid = threadIdx.x;
    const int n0 = blockIdx.x * BN;
    const int m0 = blockIdx.y * BM;

    float acc[4][4][4];
#pragma unroll
    for (int i = 0; i < 4; i++)
#pragma unroll
        for (int j = 0; j < 4; j++)
#pragma unroll
            for (int e = 0; e < 4; e++) acc[i][j][e] = 0.0f;

    gemm_mainloop(sbase, tid, A + (size_t)m0 * GK, B + (size_t)n0 * GK, acc);

    const int lane = tid & 31;
    const int warp = tid >> 5;
    const int warp_m = warp >> 2;
    const int warp_n = warp & 3;
    const int er = lane >> 2;
    const int ec = (lane & 3) * 2;
#pragma unroll
    for (int mt = 0; mt < 4; mt++) {
        const int row = m0 + warp_m * 64 + mt * 16 + er;
#pragma unroll
        for (int nt = 0; nt < 4; nt++) {
            const int col = n0 + warp_n * 32 + nt * 8 + ec;
            *(float2*)&C[(size_t)row * C_DIM + col] = make_float2(acc[mt][nt][0], acc[mt][nt][1]);
            *(float2*)&C[(size_t)(row + 8) * C_DIM + col] = make_float2(acc[mt][nt][2], acc[mt][nt][3]);
        }
    }
}

// ---------------------------------------------------------------------------
// Banded causal attention — flash-style, register-resident S/P.
// NEW: QT=128 queries/block, 256 threads (8 warps). Warp w owns rows
// 16w..16w+15 and computes S/PV over ONLY its 144-key sliding window
// (staged buffer rows 16w..16w+143), cutting mma count 25% and staged
// gmem traffic 29% vs the QT=64 version. K/V staged rows: t0-128..t0+127.
// ---------------------------------------------------------------------------
#define QT 128
#define KT2 256
#define AROW 144
#define OFF_Q 0              // 128*144 = 18432
#define OFF_K 18432          // 256*144 = 36864
#define OFF_V 55296          // 36864
#define ATTN_SMEM 92160

__global__ __launch_bounds__(256) void attn_mma(const __half* __restrict__ qq,
                                                const __half* __restrict__ kk,
                                                const __half* __restrict__ vv,
                                                __half* __restrict__ yy) {
    extern __shared__ __align__(128) char smem[];
    const uint32_t sbase = smem_u32(smem);
    const int h   = blockIdx.y;
    const int t0  = blockIdx.x * QT;
    const int tid = threadIdx.x;
    const int hoff = h * DHEAD;

    // ---- stage Q (128 rows) and K/V (256 rows each) ----
    for (int idx = tid; idx < QT * 8; idx += 256) {
        int row = idx >> 3, c = idx & 7;
        size_t src = (size_t)(t0 + row) * C_DIM + hoff + c * 8;
        cp16(sbase + OFF_Q + row * AROW + c * 16, qq + src);
    }
    for (int idx = tid; idx < KT2 * 8; idx += 256) {
        int row = idx >> 3, c = idx & 7;
        int jg = t0 - BANDW + row;
        uint32_t d = row * AROW + c * 16;
        if (jg >= 0) {
            size_t src = (size_t)jg * C_DIM + hoff + c * 8;
            cp16(sbase + OFF_K + d, kk + src);
            cp16(sbase + OFF_V + d, vv + src);
        } else {
            stz16(sbase + OFF_K + d);
            stz16(sbase + OFF_V + d);
        }
    }
    cp_commit();
    asm volatile("cp.async.wait_group 0;" ::: "memory");
    __syncthreads();     // the ONLY block-wide barrier

    const int lane = tid & 31;
    const int w    = tid >> 5;          // warp 0..7 -> rows 16w..16w+15
    const int sel  = lane >> 3;
    const int l7   = lane & 7;
    const int r    = lane >> 2;         // fragment row within m16
    const int c2   = (lane & 3) * 2;    // fragment col pair within n8

    // ---- Phase A: S = Q@K^T over warp's 144-key window (18 n8 tiles) ----
    float sacc[18][4];
#pragma unroll
    for (int m = 0; m < 18; m++)
#pragma unroll
        for (int e = 0; e < 4; e++) sacc[m][e] = 0.0f;

    const uint32_t sQ = sbase + OFF_Q +
        (uint32_t)((w * 16 + (sel & 1) * 8 + l7) * AROW + (sel >> 1) * 16);
    const uint32_t sK = sbase + OFF_K +
        (uint32_t)((w * 16 + (sel >> 1) * 8 + l7) * AROW + (sel & 1) * 16);

#pragma unroll
    for (int ks = 0; ks < 4; ks++) {
        uint32_t Qv[4];
        ldm_x4(Qv, sQ + ks * 32);
#pragma unroll
        for (int p = 0; p < 9; p++) {
            uint32_t rb[4];
            ldm_x4(rb, sK + p * (16 * AROW) + ks * 32);
            uint32_t B0[2] = {rb[0], rb[1]};
            uint32_t B1[2] = {rb[2], rb[3]};
            mma16816h(sacc[2 * p], Qv, B0);
            mma16816h(sacc[2 * p + 1], Qv, B1);
        }
    }

    // ---- register softmax (rows i0 = t0+16w+r, i1 = i0+8) ----
    // buffer-local key index jl = 8m + c2 (+1); jg = t0-128+16w+jl.
    // valid(i0): jl in (r, r+128]; valid(i1): jl in (r+8, r+136]; and jg>=0.
    const int i0 = t0 + w * 16 + r;
    const int i1 = i0 + 8;
    const int jgbase = t0 - BANDW + w * 16;
    float mx0 = -1e30f, mx1 = -1e30f;
#pragma unroll
    for (int m = 0; m < 18; m++) {
        int jl0 = 8 * m + c2;
        int jl1 = jl0 + 1;
        int jg0 = jgbase + jl0, jg1 = jgbase + jl1;
        bool v00 = (jg0 >= 0) && (jl0 > r) && (jl0 <= r + 128);
        bool v01 = (jg1 >= 0) && (jl1 > r) && (jl1 <= r + 128);
        bool v10 = (jg0 >= 0) && (jl0 > r + 8) && (jl0 <= r + 136);
        bool v11 = (jg1 >= 0) && (jl1 > r + 8) && (jl1 <= r + 136);
        sacc[m][0] = v00 ? sacc[m][0] * 0.125f : -1e30f;
        sacc[m][1] = v01 ? sacc[m][1] * 0.125f : -1e30f;
        sacc[m][2] = v10 ? sacc[m][2] * 0.125f : -1e30f;
        sacc[m][3] = v11 ? sacc[m][3] * 0.125f : -1e30f;
        mx0 = fmaxf(mx0, fmaxf(sacc[m][0], sacc[m][1]));
        mx1 = fmaxf(mx1, fmaxf(sacc[m][2], sacc[m][3]));
    }
    mx0 = fmaxf(mx0, __shfl_xor_sync(0xFFFFFFFFu, mx0, 1));
    mx0 = fmaxf(mx0, __shfl_xor_sync(0xFFFFFFFFu, mx0, 2));
    mx1 = fmaxf(mx1, __shfl_xor_sync(0xFFFFFFFFu, mx1, 1));
    mx1 = fmaxf(mx1, __shfl_xor_sync(0xFFFFFFFFu, mx1, 2));

    float sum0 = 0.0f, sum1 = 0.0f;
#pragma unroll
    for (int m = 0; m < 18; m++) {
        sacc[m][0] = __expf(sacc[m][0] - mx0);
        sacc[m][1] = __expf(sacc[m][1] - mx0);
        sacc[m][2] = __expf(sacc[m][2] - mx1);
        sacc[m][3] = __expf(sacc[m][3] - mx1);
        sum0 += sacc[m][0] + sacc[m][1];
        sum1 += sacc[m][2] + sacc[m][3];
    }
    sum0 += __shfl_xor_sync(0xFFFFFFFFu, sum0, 1);
    sum0 += __shfl_xor_sync(0xFFFFFFFFu, sum0, 2);
    sum1 += __shfl_xor_sync(0xFFFFFFFFu, sum1, 1);
    sum1 += __shfl_xor_sync(0xFFFFFFFFu, sum1, 2);
    const float inv0 = 1.0f / sum0;
    const float inv1 = 1.0f / sum1;

    // ---- convert C-frags -> A-frags for PV (9 k16 tiles) ----
    uint32_t Pf[9][4];
#pragma unroll
    for (int j = 0; j < 9; j++) {
        __half2 a0 = __floats2half2_rn(sacc[2 * j][0] * inv0, sacc[2 * j][1] * inv0);
        __half2 a1 = __floats2half2_rn(sacc[2 * j][2] * inv1, sacc[2 * j][3] * inv1);
        __half2 a2 = __floats2half2_rn(sacc[2 * j + 1][0] * inv0, sacc[2 * j + 1][1] * inv0);
        __half2 a3 = __floats2half2_rn(sacc[2 * j + 1][2] * inv1, sacc[2 * j + 1][3] * inv1);
        Pf[j][0] = *(uint32_t*)&a0;
        Pf[j][1] = *(uint32_t*)&a1;
        Pf[j][2] = *(uint32_t*)&a2;
        Pf[j][3] = *(uint32_t*)&a3;
    }

    // ---- Phase B: O = P@V (K=144 = 9 k16 tiles, N=64 = 8 n8 tiles) ----
    float oacc[8][4];
#pragma unroll
    for (int n = 0; n < 8; n++)
#pragma unroll
        for (int e = 0; e < 4; e++) oacc[n][e] = 0.0f;

    const uint32_t sV = sbase + OFF_V +
        (uint32_t)((w * 16 + (sel & 1) * 8 + l7) * AROW + (sel >> 1) * 16);
#pragma unroll
    for (int kt = 0; kt < 9; kt++) {
#pragma unroll
        for (int nb = 0; nb < 4; nb++) {
            uint32_t rb[4];
            ldm_x4t(rb, sV + kt * (16 * AROW) + nb * 32);
            uint32_t B0[2] = {rb[0], rb[1]};
            uint32_t B1[2] = {rb[2], rb[3]};
            mma16816h(oacc[2 * nb], Pf[kt], B0);
            mma16816h(oacc[2 * nb + 1], Pf[kt], B1);
        }
    }

    // ---- epilogue: direct fp16 stores ----
#pragma unroll
    for (int nt = 0; nt < 8; nt++) {
        const int col = hoff + 8 * nt + c2;
        *(__half2*)&yy[(size_t)i0 * C_DIM + col] = __floats2half2_rn(oacc[nt][0], oacc[nt][1]);
        *(__half2*)&yy[(size_t)i1 * C_DIM + col] = __floats2half2_rn(oacc[nt][2], oacc[nt][3]);
    }
}

// ---------------------------------------------------------------------------
extern "C" void kernel_launch(void* const* d_in, const int* in_sizes, int n_in,
                              void* d_out, int out_size) {
    const float* x  = (const float*)d_in[0];
    const float* Wq = (const float*)d_in[1];
    const float* Wk = (const float*)d_in[2];
    const float* Wv = (const float*)d_in[3];
    const float* Wo = (const float*)d_in[4];
    float* out = (float*)d_out;

    __half *xh, *qh, *kh, *vh, *ah, *w;
    cudaGetSymbolAddress((void**)&xh, g_x);
    cudaGetSymbolAddress((void**)&qh, g_q);
    cudaGetSymbolAddress((void**)&kh, g_k);
    cudaGetSymbolAddress((void**)&vh, g_v);
    cudaGetSymbolAddress((void**)&ah, g_a);
    cudaGetSymbolAddress((void**)&w, g_w);

    cudaFuncSetAttribute(mma_gemm_qkv, cudaFuncAttributeMaxDynamicSharedMemorySize, GEMM_SMEM);
    cudaFuncSetAttribute(mma_gemm_f32, cudaFuncAttributeMaxDynamicSharedMemorySize, GEMM_SMEM);
    cudaFuncSetAttribute(attn_mma, cudaFuncAttributeMaxDynamicSharedMemorySize, ATTN_SMEM);

    const size_t WSZ = (size_t)C_DIM * C_DIM;

    conv_all_kernel<<<dim3(T_SEQ * C_DIM / 4 / 256, 5), 256>>>(x, Wq, Wk, Wv, Wo, xh, w);

    mma_gemm_qkv<<<dim3(24, 32), 256, GEMM_SMEM>>>(xh, w, qh, kh, vh);

    attn_mma<<<dim3(T_SEQ / QT, NH), 256, ATTN_SMEM>>>(qh, kh, vh, ah);

    mma_gemm_f32<<<dim3(8, 32), 256, GEMM_SMEM>>>(ah, w + 3 * WSZ, out);
}